// round 2
// baseline (speedup 1.0000x reference)
#include <cuda_runtime.h>
#include <cstdint>

#define MAX_NODES 100000
#define MAX_EDGES 1600000

// Scratch (static device globals; no allocation anywhere)
__device__ __align__(16) float g_deg[MAX_NODES];
__device__ __align__(16) float g_agg1[MAX_NODES * 16];
__device__ __align__(16) float g_y[MAX_NODES * 4];     // x1 @ W2_l, padded, [3]=0
__device__ __align__(16) float g_z[MAX_NODES * 4];     // x1 @ W2_r, padded
__device__ __align__(16) float g_agg2[MAX_NODES * 4];

// ---------------------------------------------------------------------------
// Kernel Z: zero the accumulators (deg, agg1, agg2)
// ---------------------------------------------------------------------------
__global__ void k_zero(int n) {
    int i = blockIdx.x * blockDim.x + threadIdx.x;
    int total = n * 16;
    for (; i < total; i += gridDim.x * blockDim.x) {
        g_agg1[i] = 0.0f;
        if (i < n) g_deg[i] = 0.0f;
        if (i < n * 4) g_agg2[i] = 0.0f;
    }
}

// ---------------------------------------------------------------------------
// Kernel A: edge pass 1 — scatter feature[src] into agg1[dst] (16-dim) + degree
// 4 lanes per edge; each lane handles one float4 of the 16-float row.
// edge_index is int32 (JAX x64 disabled downcasts int64 -> int32).
// ---------------------------------------------------------------------------
__global__ void k_edge1(const int* __restrict__ ei,
                        const float4* __restrict__ feat4, int E, int N) {
    long long gid = (long long)blockIdx.x * blockDim.x + threadIdx.x;
    int eid = (int)(gid >> 2);
    int comp = (int)(gid & 3);
    if (eid >= E) return;
    int src = ei[eid];
    int dst = ei[E + eid];
    if ((unsigned)src >= (unsigned)N || (unsigned)dst >= (unsigned)N) return;
    float4 v = __ldg(&feat4[(size_t)src * 4 + comp]);
    float* p = &g_agg1[(size_t)dst * 16 + comp * 4];
    asm volatile("red.global.add.v4.f32 [%0], {%1, %2, %3, %4};"
                 :: "l"(p), "f"(v.x), "f"(v.y), "f"(v.z), "f"(v.w) : "memory");
    if (comp == 0) {
        asm volatile("red.global.add.f32 [%0], %1;"
                     :: "l"(&g_deg[dst]), "f"(1.0f) : "memory");
    }
}

// ---------------------------------------------------------------------------
// Kernel B: per-node layer-1 + fold layer-2 weights.
// One warp per node. Lane l owns output columns {l, l+32, l+64, l+96}.
//   x1 = relu( (agg1*inv_deg) @ W1_l + b1 + feature @ W1_r )   [never stored]
//   y  = x1 @ W2_l  (3)    z = x1 @ W2_r  (3)   -> padded stride-4
// ---------------------------------------------------------------------------
__global__ void k_node1(const float* __restrict__ feat,
                        const float* __restrict__ W1l,
                        const float* __restrict__ b1,
                        const float* __restrict__ W1r,
                        const float* __restrict__ W2l,
                        const float* __restrict__ W2r, int N) {
    __shared__ float sW1l[16 * 128];
    __shared__ float sW1r[16 * 128];
    __shared__ float sb1[128];
    __shared__ float sW2l[128 * 3];
    __shared__ float sW2r[128 * 3];

    int tid = threadIdx.x;
    for (int i = tid; i < 2048; i += blockDim.x) { sW1l[i] = W1l[i]; sW1r[i] = W1r[i]; }
    for (int i = tid; i < 128; i += blockDim.x) sb1[i] = b1[i];
    for (int i = tid; i < 384; i += blockDim.x) { sW2l[i] = W2l[i]; sW2r[i] = W2r[i]; }
    __syncthreads();

    int gwarp = (blockIdx.x * blockDim.x + tid) >> 5;
    int lane = tid & 31;
    if (gwarp >= N) return;
    int n = gwarp;

    float invd = 1.0f / fmaxf(g_deg[n], 1.0f);
    float fv = 0.0f, mv = 0.0f;
    if (lane < 16) {
        fv = feat[(size_t)n * 16 + lane];
        mv = g_agg1[(size_t)n * 16 + lane] * invd;
    }

    float a0 = sb1[lane], a1 = sb1[lane + 32], a2 = sb1[lane + 64], a3 = sb1[lane + 96];
#pragma unroll
    for (int k = 0; k < 16; k++) {
        float fk = __shfl_sync(0xffffffffu, fv, k);
        float mk = __shfl_sync(0xffffffffu, mv, k);
        const float* wl = &sW1l[k * 128];
        const float* wr = &sW1r[k * 128];
        a0 = fmaf(mk, wl[lane],      fmaf(fk, wr[lane],      a0));
        a1 = fmaf(mk, wl[lane + 32], fmaf(fk, wr[lane + 32], a1));
        a2 = fmaf(mk, wl[lane + 64], fmaf(fk, wr[lane + 64], a2));
        a3 = fmaf(mk, wl[lane + 96], fmaf(fk, wr[lane + 96], a3));
    }
    a0 = fmaxf(a0, 0.0f); a1 = fmaxf(a1, 0.0f);
    a2 = fmaxf(a2, 0.0f); a3 = fmaxf(a3, 0.0f);

    float py[3], pz[3];
#pragma unroll
    for (int t = 0; t < 3; t++) {
        py[t] = a0 * sW2l[lane * 3 + t]
              + a1 * sW2l[(lane + 32) * 3 + t]
              + a2 * sW2l[(lane + 64) * 3 + t]
              + a3 * sW2l[(lane + 96) * 3 + t];
        pz[t] = a0 * sW2r[lane * 3 + t]
              + a1 * sW2r[(lane + 32) * 3 + t]
              + a2 * sW2r[(lane + 64) * 3 + t]
              + a3 * sW2r[(lane + 96) * 3 + t];
    }
#pragma unroll
    for (int off = 16; off > 0; off >>= 1) {
#pragma unroll
        for (int t = 0; t < 3; t++) {
            py[t] += __shfl_down_sync(0xffffffffu, py[t], off);
            pz[t] += __shfl_down_sync(0xffffffffu, pz[t], off);
        }
    }
    if (lane == 0) {
        float4 yv = make_float4(py[0], py[1], py[2], 0.0f);
        float4 zv = make_float4(pz[0], pz[1], pz[2], 0.0f);
        *(float4*)&g_y[(size_t)n * 4] = yv;
        *(float4*)&g_z[(size_t)n * 4] = zv;
    }
}

// ---------------------------------------------------------------------------
// Kernel C: edge pass 2 — scatter y[src] (3-dim, padded to 4) into agg2[dst]
// ---------------------------------------------------------------------------
__global__ void k_edge2(const int* __restrict__ ei, int E, int N) {
    int eid = blockIdx.x * blockDim.x + threadIdx.x;
    if (eid >= E) return;
    int src = ei[eid];
    int dst = ei[E + eid];
    if ((unsigned)src >= (unsigned)N || (unsigned)dst >= (unsigned)N) return;
    float4 v = *(const float4*)&g_y[(size_t)src * 4];
    float* p = &g_agg2[(size_t)dst * 4];
    asm volatile("red.global.add.v4.f32 [%0], {%1, %2, %3, %4};"
                 :: "l"(p), "f"(v.x), "f"(v.y), "f"(v.z), "f"(v.w) : "memory");
}

// ---------------------------------------------------------------------------
// Kernel D: epilogue — out = agg2 * inv_deg + b2 + z
// ---------------------------------------------------------------------------
__global__ void k_out(const float* __restrict__ b2, float* __restrict__ out, int N) {
    int i = blockIdx.x * blockDim.x + threadIdx.x;
    if (i >= N) return;
    float invd = 1.0f / fmaxf(g_deg[i], 1.0f);
    float4 a = *(const float4*)&g_agg2[(size_t)i * 4];
    float4 z = *(const float4*)&g_z[(size_t)i * 4];
    out[(size_t)i * 3 + 0] = a.x * invd + b2[0] + z.x;
    out[(size_t)i * 3 + 1] = a.y * invd + b2[1] + z.y;
    out[(size_t)i * 3 + 2] = a.z * invd + b2[2] + z.z;
}

// ---------------------------------------------------------------------------
extern "C" void kernel_launch(void* const* d_in, const int* in_sizes, int n_in,
                              void* d_out, int out_size) {
    const float* feature = (const float*)d_in[0];
    const int*   ei      = (const int*)d_in[1];   // int32: JAX x64-disabled downcast
    // d_in[2] = edge_type (unused)
    const float* W1l = (const float*)d_in[3];
    const float* b1  = (const float*)d_in[4];
    const float* W1r = (const float*)d_in[5];
    const float* W2l = (const float*)d_in[6];
    const float* b2  = (const float*)d_in[7];
    const float* W2r = (const float*)d_in[8];
    float* out = (float*)d_out;

    int N = in_sizes[0] / 16;
    int E = in_sizes[1] / 2;

    // Z: zero accumulators
    {
        int total = N * 16;
        int blocks = (total + 255) / 256;
        if (blocks > 4096) blocks = 4096;
        k_zero<<<blocks, 256>>>(N);
    }
    // A: layer-1 scatter (4 lanes/edge)
    {
        long long threads = 4LL * E;
        int blocks = (int)((threads + 255) / 256);
        k_edge1<<<blocks, 256>>>(ei, (const float4*)feature, E, N);
    }
    // B: node layer-1 + fold layer-2 weights (1 warp/node)
    {
        int blocks = (N * 32 + 255) / 256;
        k_node1<<<blocks, 256>>>(feature, W1l, b1, W1r, W2l, W2r, N);
    }
    // C: layer-2 scatter (1 thread/edge)
    {
        int blocks = (E + 255) / 256;
        k_edge2<<<blocks, 256>>>(ei, E, N);
    }
    // D: epilogue
    {
        int blocks = (N + 255) / 256;
        k_out<<<blocks, 256>>>(b2, out, N);
    }
}